// round 3
// baseline (speedup 1.0000x reference)
#include <cuda_runtime.h>
#include <math.h>

#define NPAIR 32      // 64 real batches packed as 32 complex images
#define HIN   512
#define WIN   512
#define NP    768     // padded size (both dims)
#define PAD   128
#define SMEM_FLOAT2 (4*NP*2 + NP)          // A[4][768] + B[4][768] + E[768]
#define SMEM_BYTES  (SMEM_FLOAT2 * sizeof(float2))   // 55296

__device__ float2 g_buf[NPAIR * NP * NP];  // 151 MB scratch
__device__ float2 g_E[NP];                 // e^{-2*pi*i*m/768}

static __device__ __forceinline__ float2 cmul(float2 a, float2 b) {
    return make_float2(a.x*b.x - a.y*b.y, a.x*b.y + a.y*b.x);
}
static __device__ __forceinline__ float2 cadd(float2 a, float2 b) { return make_float2(a.x+b.x, a.y+b.y); }
static __device__ __forceinline__ float2 csub(float2 a, float2 b) { return make_float2(a.x-b.x, a.y-b.y); }
static __device__ __forceinline__ float2 cconj(float2 a) { return make_float2(a.x, -a.y); }

__global__ void k_init_E() {
    int t = threadIdx.x;
    if (t < NP) {
        double a = -2.0 * 3.14159265358979323846 * (double)t / (double)NP;
        g_E[t] = make_float2((float)cos(a), (float)sin(a));
    }
}

// ---------------- mixed-radix Stockham FFT of length 768 = 4*4*4*4*3 ----------------
// 64 threads per line (ty in [0,64)). S = element stride in the smem buffers.
// Twiddle table E[m] = e^{-2pi i m / 768}; INV conjugates.

template<int S, bool INV, int NS, int TWF>
static __device__ __forceinline__ void r4_stage(const float2* src, float2* dst,
                                                const float2* E, int ty)
{
#pragma unroll
    for (int it = 0; it < 3; it++) {
        int j = ty + (it << 6);                 // j in [0,192)
        int m = j & (NS - 1);                   // NS is a power of two here
        int base = ((j - m) << 2) + m;          // (j/NS)*NS*4 + m
        float2 v0 = src[j * S];
        float2 v1 = src[(j + 192) * S];
        float2 v2 = src[(j + 384) * S];
        float2 v3 = src[(j + 576) * S];
        if (NS > 1) {
            float2 w1 = E[m * TWF];
            float2 w2 = E[2 * m * TWF];
            float2 w3 = E[3 * m * TWF];
            if (INV) { w1.y = -w1.y; w2.y = -w2.y; w3.y = -w3.y; }
            v1 = cmul(v1, w1); v2 = cmul(v2, w2); v3 = cmul(v3, w3);
        }
        float2 t0 = cadd(v0, v2), t1 = csub(v0, v2);
        float2 t2 = cadd(v1, v3), t3 = csub(v1, v3);
        float2 it3 = make_float2(-t3.y, t3.x);  // i * t3
        dst[base * S]            = cadd(t0, t2);
        dst[(base + 2*NS) * S]   = csub(t0, t2);
        if (!INV) {
            dst[(base + NS) * S]   = csub(t1, it3);
            dst[(base + 3*NS) * S] = cadd(t1, it3);
        } else {
            dst[(base + NS) * S]   = cadd(t1, it3);
            dst[(base + 3*NS) * S] = csub(t1, it3);
        }
    }
    __syncthreads();
}

template<int S, bool INV>
static __device__ __forceinline__ void r3_stage(const float2* src, float2* dst,
                                                const float2* E, int ty)
{
    // NS = 256, TWF = 1
#pragma unroll
    for (int it = 0; it < 4; it++) {
        int j = ty + (it << 6);                 // j in [0,256)
        float2 v0 = src[j * S];
        float2 v1 = src[(j + 256) * S];
        float2 v2 = src[(j + 512) * S];
        float2 w1 = E[j];
        float2 w2 = E[2 * j];                   // 2*j < 512 < 768, no wrap
        if (INV) { w1.y = -w1.y; w2.y = -w2.y; }
        v1 = cmul(v1, w1); v2 = cmul(v2, w2);
        float2 t = cadd(v1, v2);
        float2 u = csub(v1, v2);
        float2 x0 = cadd(v0, t);
        float2 mm = make_float2(v0.x - 0.5f * t.x, v0.y - 0.5f * t.y);
        const float d = INV ? 0.8660254037844386f : -0.8660254037844386f;
        float2 idu = make_float2(-d * u.y, d * u.x);  // i*d*u
        dst[j * S]         = x0;
        dst[(j + 256) * S] = cadd(mm, idu);
        dst[(j + 512) * S] = csub(mm, idu);
    }
    __syncthreads();
}

// Result lands in Y (second argument).
template<int S, bool INV>
static __device__ __forceinline__ void fft768(float2* X, float2* Y, const float2* E, int ty)
{
    r4_stage<S, INV, 1, 192>(X, Y, E, ty);
    r4_stage<S, INV, 4, 48>(Y, X, E, ty);
    r4_stage<S, INV, 16, 12>(X, Y, E, ty);
    r4_stage<S, INV, 64, 3>(Y, X, E, ty);
    r3_stage<S, INV>(X, Y, E, ty);
}

// ---------------- Pass 1: pad + pack pairs + forward row FFT ----------------
__global__ __launch_bounds__(256) void k_row_fwd(const float* __restrict__ x)
{
    extern __shared__ float2 sm[];
    float2* SA = sm;
    float2* SB = sm + 4 * NP;
    float2* SE = sm + 8 * NP;
    int t = threadIdx.x;
    for (int i = t; i < NP; i += 256) SE[i] = g_E[i];
    int sub = t >> 6;
    int ty  = t & 63;
    int row = blockIdx.x * 4 + sub;             // [0, 32*768)
    int p = row / NP;
    int y = row - p * NP;
    float2* A = SA + sub * NP;
    float2* B = SB + sub * NP;
    const float* r1 = x + ((size_t)(2*p)     * HIN + (y - PAD)) * WIN;
    const float* r2 = x + ((size_t)(2*p + 1) * HIN + (y - PAD)) * WIN;
    bool yin = (y >= PAD) && (y < PAD + HIN);
#pragma unroll
    for (int i = 0; i < 12; i++) {
        int xi = ty + (i << 6);
        float2 v = make_float2(0.f, 0.f);
        if (yin && xi >= PAD && xi < PAD + WIN) {
            v.x = r1[xi - PAD];
            v.y = r2[xi - PAD];
        }
        A[xi] = v;
    }
    __syncthreads();
    fft768<1, false>(A, B, SE, ty);
    float2* o = g_buf + (size_t)row * NP;
#pragma unroll
    for (int i = 0; i < 12; i++) { int xi = ty + (i << 6); o[xi] = B[xi]; }
}

// ---------------- Pass 2: column FFT * G * column IFFT (in place) ----------------
// G replicates the reference exactly:
//   gmf[k,j] = 1/(H(k,j) H(-k,j) H(k,m(j)) H(-k,m(j))), m(j)=0 if j==0 else 385-j
// full-grid extension for j>384: conj of mirror; j==384: Re-projection (irfft
// ignores imag of the Nyquist bin). 1/768^2 ifft scale folded into G.
__global__ __launch_bounds__(256) void k_col(const float* __restrict__ w)
{
    extern __shared__ float2 sm[];
    float2* SA = sm;          // interleaved [768][4]
    float2* SB = sm + 4 * NP;
    float2* SE = sm + 8 * NP;
    int t = threadIdx.x;
    for (int i = t; i < NP; i += 256) SE[i] = g_E[i];
    int tx = t & 3;
    int ty = t >> 2;
    int p = blockIdx.x / 192;
    int g = blockIdx.x - p * 192;
    int kx = (g << 2) + tx;
    float2* base = g_buf + (size_t)p * NP * NP;
    float2* A = SA + tx;
    float2* B = SB + tx;
#pragma unroll
    for (int i = 0; i < 12; i++) {
        int y = ty + (i << 6);
        A[y << 2] = base[(size_t)y * NP + kx];
    }
    __syncthreads();
    fft768<4, false>(A, B, SE, ty);   // spectrum (over ky) now in SB

    int jp = (kx <= 384) ? kx : (NP - kx);
    int j2 = (jp == 0) ? 0 : ((jp == 384) ? 1 : (385 - jp));
    float2 D1[3], D2[3];
#pragma unroll
    for (int a = 0; a < 3; a++) {
        float2 s1 = make_float2(0.f, 0.f), s2 = make_float2(0.f, 0.f);
#pragma unroll
        for (int b = 0; b < 3; b++) {
            float wv = w[a * 3 + b];
            int i1 = (jp * b) % NP;
            int i2 = (j2 * b) % NP;
            float2 e1 = SE[i1], e2 = SE[i2];
            s1.x += wv * e1.x; s1.y += wv * e1.y;
            s2.x += wv * e2.x; s2.y += wv * e2.y;
        }
        D1[a] = s1; D2[a] = s2;
    }
    const float scale = 1.0f / ((float)NP * (float)NP);
#pragma unroll
    for (int i = 0; i < 12; i++) {
        int ky = ty + (i << 6);
        float2 e1 = SE[ky];
        int k2i = 2 * ky; if (k2i >= NP) k2i -= NP;
        float2 e2 = SE[k2i];
        float2 c1 = cconj(e1), c2 = cconj(e2);
        float2 hp1 = cadd(D1[0], cadd(cmul(e1, D1[1]), cmul(e2, D1[2])));
        float2 hm1 = cadd(D1[0], cadd(cmul(c1, D1[1]), cmul(c2, D1[2])));
        float2 hp2 = cadd(D2[0], cadd(cmul(e1, D2[1]), cmul(e2, D2[2])));
        float2 hm2 = cadd(D2[0], cadd(cmul(c1, D2[1]), cmul(c2, D2[2])));
        float2 P = cmul(cmul(hp1, hm1), cmul(hp2, hm2));
        float inv = 1.0f / (P.x * P.x + P.y * P.y);
        float2 G = make_float2(P.x * inv, -P.y * inv);
        if (kx == 384)      G.y = 0.0f;    // irfft drops imag at Nyquist column
        else if (kx > 384)  G.y = -G.y;    // Hermitian mirror half
        G.x *= scale; G.y *= scale;
        float2 v = B[ky << 2];
        B[ky << 2] = cmul(v, G);
    }
    __syncthreads();
    fft768<4, true>(B, A, SE, ty);    // result in SA
#pragma unroll
    for (int i = 0; i < 12; i++) {
        int y = ty + (i << 6);
        base[(size_t)y * NP + kx] = A[y << 2];
    }
}

// ---------------- Pass 3: inverse row FFT + unpack pairs ----------------
__global__ __launch_bounds__(256) void k_row_inv(float* __restrict__ out)
{
    extern __shared__ float2 sm[];
    float2* SA = sm;
    float2* SB = sm + 4 * NP;
    float2* SE = sm + 8 * NP;
    int t = threadIdx.x;
    for (int i = t; i < NP; i += 256) SE[i] = g_E[i];
    int sub = t >> 6;
    int ty  = t & 63;
    int row = blockIdx.x * 4 + sub;
    int p = row / NP;
    int y = row - p * NP;
    float2* A = SA + sub * NP;
    float2* B = SB + sub * NP;
    const float2* in = g_buf + (size_t)row * NP;
#pragma unroll
    for (int i = 0; i < 12; i++) { int xi = ty + (i << 6); A[xi] = in[xi]; }
    __syncthreads();
    fft768<1, true>(A, B, SE, ty);
    float* o1 = out + ((size_t)(2*p)     * NP + y) * NP;
    float* o2 = out + ((size_t)(2*p + 1) * NP + y) * NP;
#pragma unroll
    for (int i = 0; i < 12; i++) {
        int xi = ty + (i << 6);
        float2 v = B[xi];
        o1[xi] = v.x;
        o2[xi] = v.y;
    }
}

extern "C" void kernel_launch(void* const* d_in, const int* in_sizes, int n_in,
                              void* d_out, int out_size)
{
    const float* x = (const float*)d_in[0];
    const float* w = (const float*)d_in[1];
    if (n_in >= 2 && in_sizes[0] == 9) {  // safety: metadata order w,x
        const float* tmp = x; x = w; w = tmp;
    }
    float* out = (float*)d_out;

    cudaFuncSetAttribute(k_row_fwd, cudaFuncAttributeMaxDynamicSharedMemorySize, (int)SMEM_BYTES);
    cudaFuncSetAttribute(k_col,     cudaFuncAttributeMaxDynamicSharedMemorySize, (int)SMEM_BYTES);
    cudaFuncSetAttribute(k_row_inv, cudaFuncAttributeMaxDynamicSharedMemorySize, (int)SMEM_BYTES);

    k_init_E<<<1, NP>>>();
    k_row_fwd<<<NPAIR * NP / 4, 256, SMEM_BYTES>>>(x);
    k_col    <<<NPAIR * NP / 4, 256, SMEM_BYTES>>>(w);
    k_row_inv<<<NPAIR * NP / 4, 256, SMEM_BYTES>>>(out);
}

// round 5
// speedup vs baseline: 1.1945x; 1.1945x over previous
#include <cuda_runtime.h>
#include <math.h>

#define NPAIR 32      // 64 real batches packed as 32 complex images
#define HIN   512
#define WIN   512
#define NP    768     // padded size (both dims)
#define PAD   128
#define NZROWS 512    // nonzero padded rows: y in [PAD, PAD+512)

// padded smem index: insert one float2 per 16 to break stride-4/16/64 conflicts
#define P_(i) ((i) + ((i) >> 4))

#define LINEBUF 816                 // >= P_(767)+1
#define COLBUF  3264                // >= P_(3071)+1
#define SMEM_FLOAT2 (2*COLBUF + LINEBUF)   // A + B + E  (row layout fits in same)
#define SMEM_BYTES  (SMEM_FLOAT2 * sizeof(float2))   // 58752

__device__ float2 g_buf[NPAIR * NP * NP];  // 151 MB scratch
__device__ float2 g_E[NP];                 // e^{-2*pi*i*m/768}

static __device__ __forceinline__ float2 cmul(float2 a, float2 b) {
    return make_float2(a.x*b.x - a.y*b.y, a.x*b.y + a.y*b.x);
}
static __device__ __forceinline__ float2 cadd(float2 a, float2 b) { return make_float2(a.x+b.x, a.y+b.y); }
static __device__ __forceinline__ float2 csub(float2 a, float2 b) { return make_float2(a.x-b.x, a.y-b.y); }
static __device__ __forceinline__ float2 cconj(float2 a) { return make_float2(a.x, -a.y); }

__global__ void k_init_E() {
    int t = threadIdx.x;
    if (t < NP) {
        double a = -2.0 * 3.14159265358979323846 * (double)t / (double)NP;
        g_E[t] = make_float2((float)cos(a), (float)sin(a));
    }
}

// index maps: row kernels use contiguous lines, col kernel interleaves 4 lines
struct MapRow {
    __device__ __forceinline__ int operator()(int i) const { return P_(i); }
};
struct MapCol {
    int tx;
    __device__ __forceinline__ int operator()(int i) const { int b = (i << 2) + tx; return P_(b); }
};

// ---------------- mixed-radix Stockham FFT of length 768 = 4*4*4*4*3 ----------------
// 64 threads per line (ty in [0,64)). E is stored PADDED: E[P_(m)].

template<bool INV, int NS, int TWF, class M>
static __device__ __forceinline__ void r4_stage(const float2* src, float2* dst,
                                                const float2* E, int ty, M map)
{
#pragma unroll
    for (int it = 0; it < 3; it++) {
        int j = ty + (it << 6);                 // j in [0,192)
        int m = j & (NS - 1);
        int base = ((j - m) << 2) + m;
        float2 v0 = src[map(j)];
        float2 v1 = src[map(j + 192)];
        float2 v2 = src[map(j + 384)];
        float2 v3 = src[map(j + 576)];
        if (NS > 1) {
            float2 w1 = E[P_(m * TWF)];
            float2 w2 = E[P_(2 * m * TWF)];
            float2 w3 = E[P_(3 * m * TWF)];
            if (INV) { w1.y = -w1.y; w2.y = -w2.y; w3.y = -w3.y; }
            v1 = cmul(v1, w1); v2 = cmul(v2, w2); v3 = cmul(v3, w3);
        }
        float2 t0 = cadd(v0, v2), t1 = csub(v0, v2);
        float2 t2 = cadd(v1, v3), t3 = csub(v1, v3);
        float2 it3 = make_float2(-t3.y, t3.x);  // i * t3
        dst[map(base)]          = cadd(t0, t2);
        dst[map(base + 2*NS)]   = csub(t0, t2);
        if (!INV) {
            dst[map(base + NS)]   = csub(t1, it3);
            dst[map(base + 3*NS)] = cadd(t1, it3);
        } else {
            dst[map(base + NS)]   = cadd(t1, it3);
            dst[map(base + 3*NS)] = csub(t1, it3);
        }
    }
    __syncthreads();
}

template<bool INV, class M>
static __device__ __forceinline__ void r3_stage(const float2* src, float2* dst,
                                                const float2* E, int ty, M map)
{
    // NS = 256, TWF = 1
#pragma unroll
    for (int it = 0; it < 4; it++) {
        int j = ty + (it << 6);                 // j in [0,256)
        float2 v0 = src[map(j)];
        float2 v1 = src[map(j + 256)];
        float2 v2 = src[map(j + 512)];
        float2 w1 = E[P_(j)];
        float2 w2 = E[P_(2 * j)];
        if (INV) { w1.y = -w1.y; w2.y = -w2.y; }
        v1 = cmul(v1, w1); v2 = cmul(v2, w2);
        float2 t = cadd(v1, v2);
        float2 u = csub(v1, v2);
        float2 x0 = cadd(v0, t);
        float2 mm = make_float2(v0.x - 0.5f * t.x, v0.y - 0.5f * t.y);
        const float d = INV ? 0.8660254037844386f : -0.8660254037844386f;
        float2 idu = make_float2(-d * u.y, d * u.x);  // i*d*u
        dst[map(j)]         = x0;
        dst[map(j + 256)]   = cadd(mm, idu);
        dst[map(j + 512)]   = csub(mm, idu);
    }
    __syncthreads();
}

// Result lands in Y (second argument).
template<bool INV, class M>
static __device__ __forceinline__ void fft768(float2* X, float2* Y, const float2* E, int ty, M map)
{
    r4_stage<INV, 1, 192>(X, Y, E, ty, map);
    r4_stage<INV, 4, 48>(Y, X, E, ty, map);
    r4_stage<INV, 16, 12>(X, Y, E, ty, map);
    r4_stage<INV, 64, 3>(Y, X, E, ty, map);
    r3_stage<INV>(X, Y, E, ty, map);
}

// ---------------- Pass 1: pad + pack pairs + forward row FFT (512 rows/image only) ----------------
__global__ __launch_bounds__(256) void k_row_fwd(const float* __restrict__ x)
{
    extern __shared__ float2 sm[];
    float2* SA = sm;
    float2* SB = sm + COLBUF;
    float2* SE = sm + 2 * COLBUF;
    int t = threadIdx.x;
    for (int i = t; i < NP; i += 256) SE[P_(i)] = g_E[i];
    int sub = t >> 6;
    int ty  = t & 63;
    int row4 = blockIdx.x * 4 + sub;            // [0, 32*512)
    int p = row4 >> 9;                          // /512
    int r = row4 & 511;
    int y = PAD + r;
    float2* A = SA + sub * LINEBUF;
    float2* B = SB + sub * LINEBUF;
    MapRow map;
    const float* r1 = x + ((size_t)(2*p)     * HIN + r) * WIN;
    const float* r2 = x + ((size_t)(2*p + 1) * HIN + r) * WIN;
#pragma unroll
    for (int i = 0; i < 12; i++) {
        int xi = ty + (i << 6);
        float2 v = make_float2(0.f, 0.f);
        if (xi >= PAD && xi < PAD + WIN) {
            v.x = r1[xi - PAD];
            v.y = r2[xi - PAD];
        }
        A[map(xi)] = v;
    }
    __syncthreads();
    fft768<false>(A, B, SE, ty, map);
    float2* o = g_buf + ((size_t)p * NP + y) * NP;
#pragma unroll
    for (int i = 0; i < 12; i++) { int xi = ty + (i << 6); o[xi] = B[map(xi)]; }
}

// ---------------- Pass 2: column FFT * G * column IFFT (in place, rows<PAD / >=PAD+512 known zero) ----------------
__global__ __launch_bounds__(256) void k_col(const float* __restrict__ w)
{
    extern __shared__ float2 sm[];
    float2* SA = sm;          // interleaved [768][4], padded
    float2* SB = sm + COLBUF;
    float2* SE = sm + 2 * COLBUF;
    int t = threadIdx.x;
    for (int i = t; i < NP; i += 256) SE[P_(i)] = g_E[i];
    int tx = t & 3;
    int ty = t >> 2;
    int p = blockIdx.x / 192;
    int g = blockIdx.x - p * 192;
    int kx = (g << 2) + tx;
    float2* base = g_buf + (size_t)p * NP * NP;
    MapCol map; map.tx = tx;
#pragma unroll
    for (int i = 0; i < 12; i++) {
        int y = ty + (i << 6);
        float2 v = make_float2(0.f, 0.f);
        if (y >= PAD && y < PAD + NZROWS)
            v = base[(size_t)y * NP + kx];
        SA[map(y)] = v;
    }
    __syncthreads();
    fft768<false>(SA, SB, SE, ty, map);   // spectrum (over ky) now in SB

    int jp = (kx <= 384) ? kx : (NP - kx);
    int j2 = (jp == 0) ? 0 : ((jp == 384) ? 1 : (385 - jp));
    float2 D1[3], D2[3];
#pragma unroll
    for (int a = 0; a < 3; a++) {
        float2 s1 = make_float2(0.f, 0.f), s2 = make_float2(0.f, 0.f);
#pragma unroll
        for (int b = 0; b < 3; b++) {
            float wv = w[a * 3 + b];
            int i1 = (jp * b) % NP;
            int i2 = (j2 * b) % NP;
            float2 e1 = SE[P_(i1)], e2 = SE[P_(i2)];
            s1.x += wv * e1.x; s1.y += wv * e1.y;
            s2.x += wv * e2.x; s2.y += wv * e2.y;
        }
        D1[a] = s1; D2[a] = s2;
    }
    const float scale = 1.0f / ((float)NP * (float)NP);
#pragma unroll
    for (int i = 0; i < 12; i++) {
        int ky = ty + (i << 6);
        float2 e1 = SE[P_(ky)];
        int k2i = 2 * ky; if (k2i >= NP) k2i -= NP;
        float2 e2 = SE[P_(k2i)];
        float2 c1 = cconj(e1), c2 = cconj(e2);
        float2 hp1 = cadd(D1[0], cadd(cmul(e1, D1[1]), cmul(e2, D1[2])));
        float2 hm1 = cadd(D1[0], cadd(cmul(c1, D1[1]), cmul(c2, D1[2])));
        float2 hp2 = cadd(D2[0], cadd(cmul(e1, D2[1]), cmul(e2, D2[2])));
        float2 hm2 = cadd(D2[0], cadd(cmul(c1, D2[1]), cmul(c2, D2[2])));
        float2 P = cmul(cmul(hp1, hm1), cmul(hp2, hm2));
        float inv = 1.0f / (P.x * P.x + P.y * P.y);
        float2 G = make_float2(P.x * inv, -P.y * inv);
        if (kx == 384)      G.y = 0.0f;    // irfft drops imag at Nyquist column
        else if (kx > 384)  G.y = -G.y;    // Hermitian mirror half
        G.x *= scale; G.y *= scale;
        float2 v = SB[map(ky)];
        SB[map(ky)] = cmul(v, G);
    }
    __syncthreads();
    fft768<true>(SB, SA, SE, ty, map);    // result in SA
#pragma unroll
    for (int i = 0; i < 12; i++) {
        int y = ty + (i << 6);
        base[(size_t)y * NP + kx] = SA[map(y)];
    }
}

// ---------------- Pass 3: inverse row FFT + unpack pairs ----------------
__global__ __launch_bounds__(256) void k_row_inv(float* __restrict__ out)
{
    extern __shared__ float2 sm[];
    float2* SA = sm;
    float2* SB = sm + COLBUF;
    float2* SE = sm + 2 * COLBUF;
    int t = threadIdx.x;
    for (int i = t; i < NP; i += 256) SE[P_(i)] = g_E[i];
    int sub = t >> 6;
    int ty  = t & 63;
    int row = blockIdx.x * 4 + sub;
    int p = row / NP;
    int y = row - p * NP;
    float2* A = SA + sub * LINEBUF;
    float2* B = SB + sub * LINEBUF;
    MapRow map;
    const float2* in = g_buf + (size_t)row * NP;
#pragma unroll
    for (int i = 0; i < 12; i++) { int xi = ty + (i << 6); A[map(xi)] = in[xi]; }
    __syncthreads();
    fft768<true>(A, B, SE, ty, map);
    float* o1 = out + ((size_t)(2*p)     * NP + y) * NP;
    float* o2 = out + ((size_t)(2*p + 1) * NP + y) * NP;
#pragma unroll
    for (int i = 0; i < 12; i++) {
        int xi = ty + (i << 6);
        float2 v = B[map(xi)];
        o1[xi] = v.x;
        o2[xi] = v.y;
    }
}

extern "C" void kernel_launch(void* const* d_in, const int* in_sizes, int n_in,
                              void* d_out, int out_size)
{
    const float* x = (const float*)d_in[0];
    const float* w = (const float*)d_in[1];
    if (n_in >= 2 && in_sizes[0] == 9) {  // safety: metadata order w,x
        const float* tmp = x; x = w; w = tmp;
    }
    float* out = (float*)d_out;

    cudaFuncSetAttribute(k_row_fwd, cudaFuncAttributeMaxDynamicSharedMemorySize, (int)SMEM_BYTES);
    cudaFuncSetAttribute(k_col,     cudaFuncAttributeMaxDynamicSharedMemorySize, (int)SMEM_BYTES);
    cudaFuncSetAttribute(k_row_inv, cudaFuncAttributeMaxDynamicSharedMemorySize, (int)SMEM_BYTES);

    k_init_E<<<1, NP>>>();
    k_row_fwd<<<NPAIR * NZROWS / 4, 256, SMEM_BYTES>>>(x);
    k_col    <<<NPAIR * 192, 256, SMEM_BYTES>>>(w);
    k_row_inv<<<NPAIR * NP / 4, 256, SMEM_BYTES>>>(out);
}

// round 6
// speedup vs baseline: 1.7009x; 1.4239x over previous
#include <cuda_runtime.h>
#include <math.h>

#define NPAIR 32      // 64 real batches packed as 32 complex images
#define HIN   512
#define WIN   512
#define NP    768     // padded size (both dims)
#define PAD   128
#define NZROWS 512    // nonzero padded rows: y in [PAD, PAD+512)

// padded smem element index: +1 float2 per 16 to break power-of-2 stride conflicts
#define P_(i) ((i) + ((i) >> 4))

#define BUF   3264    // block-wide float2 data buffer: >= P_(3071)+1
#define LLEN  816     // per-line stride in row kernels: >= P_(767)+1
#define EBUF  816

__device__ float2 g_buf[NPAIR * NP * NP];  // 151 MB scratch
__device__ float2 g_E[NP];                 // e^{-2*pi*i*m/768}

static __device__ __forceinline__ float2 cmul(float2 a, float2 b) {
    return make_float2(a.x*b.x - a.y*b.y, a.x*b.y + a.y*b.x);
}
static __device__ __forceinline__ float2 cadd(float2 a, float2 b) { return make_float2(a.x+b.x, a.y+b.y); }
static __device__ __forceinline__ float2 csub(float2 a, float2 b) { return make_float2(a.x-b.x, a.y-b.y); }
static __device__ __forceinline__ float2 cconj(float2 a) { return make_float2(a.x, -a.y); }
static __device__ __forceinline__ float2 mul_mi(float2 a) { return make_float2(a.y, -a.x); }  // *(-i)
static __device__ __forceinline__ float2 mul_pi(float2 a) { return make_float2(-a.y, a.x); }  // *(+i)

__global__ void k_init_E() {
    int t = threadIdx.x;
    if (t < NP) {
        double a = -2.0 * 3.14159265358979323846 * (double)t / (double)NP;
        g_E[t] = make_float2((float)cos(a), (float)sin(a));
    }
}

// ---------------- register DFT kernels ----------------
template<bool INV>
static __device__ __forceinline__ void dft4(float2 v[4]) {
    float2 t0 = cadd(v[0], v[2]), t1 = csub(v[0], v[2]);
    float2 t2 = cadd(v[1], v[3]), t3 = csub(v[1], v[3]);
    float2 jt3 = INV ? mul_pi(t3) : mul_mi(t3);
    v[0] = cadd(t0, t2); v[2] = csub(t0, t2);
    v[1] = cadd(t1, jt3); v[3] = csub(t1, jt3);
}

template<bool INV>
static __device__ __forceinline__ void dft8(float2 v[8]) {
    float2 e[4] = {v[0], v[2], v[4], v[6]};
    float2 o[4] = {v[1], v[3], v[5], v[7]};
    dft4<INV>(e); dft4<INV>(o);
    const float rh = 0.70710678118654752f;
    o[1] = cmul(o[1], make_float2(rh, INV ? rh : -rh));
    o[2] = INV ? mul_pi(o[2]) : mul_mi(o[2]);
    o[3] = cmul(o[3], make_float2(-rh, INV ? rh : -rh));
#pragma unroll
    for (int k = 0; k < 4; k++) { v[k] = cadd(e[k], o[k]); v[k+4] = csub(e[k], o[k]); }
}

// 12-point DFT, natural-order in and out.  12 = 4 x 3 Cooley-Tukey.
template<bool INV>
static __device__ __forceinline__ void dft12(float2 v[12]) {
    const float H = 0.5f, S = 0.8660254037844386f;
    float2 c0[4], c1[4], c2[4];
    {
        float2 b[4];
        b[0]=v[0]; b[1]=v[3]; b[2]=v[6]; b[3]=v[9];  dft4<INV>(b);
        c0[0]=b[0]; c0[1]=b[1]; c0[2]=b[2]; c0[3]=b[3];
        b[0]=v[1]; b[1]=v[4]; b[2]=v[7]; b[3]=v[10]; dft4<INV>(b);
        c1[0]=b[0]; c1[1]=b[1]; c1[2]=b[2]; c1[3]=b[3];
        b[0]=v[2]; b[1]=v[5]; b[2]=v[8]; b[3]=v[11]; dft4<INV>(b);
        c2[0]=b[0]; c2[1]=b[1]; c2[2]=b[2]; c2[3]=b[3];
    }
    // twiddles: c1[k] *= W12^k,  c2[k] *= W12^{2k}   (conj if INV)
    const float sgn = INV ? 1.f : -1.f;
    c1[1] = cmul(c1[1], make_float2(S, sgn*H));
    c1[2] = cmul(c1[2], make_float2(H, sgn*S));
    c1[3] = INV ? mul_pi(c1[3]) : mul_mi(c1[3]);
    c2[1] = cmul(c2[1], make_float2(H,  sgn*S));
    c2[2] = cmul(c2[2], make_float2(-H, sgn*S));
    c2[3] = make_float2(-c2[3].x, -c2[3].y);
    // DFT_3 over n2 for each k1; outputs X[4*k2 + k1]
    const float d = INV ? S : -S;
#pragma unroll
    for (int k1 = 0; k1 < 4; k1++) {
        float2 t = cadd(c1[k1], c2[k1]);
        float2 u = csub(c1[k1], c2[k1]);
        float2 x0 = cadd(c0[k1], t);
        float2 m = make_float2(c0[k1].x - 0.5f*t.x, c0[k1].y - 0.5f*t.y);
        float2 idu = make_float2(-d*u.y, d*u.x);
        v[k1]     = x0;
        v[4 + k1] = cadd(m, idu);
        v[8 + k1] = csub(m, idu);
    }
}

// ---------------- Stockham stages: 768 = 8(NS=1) * 8(NS=8) * 12(NS=64) ----------------
struct MapRow {
    int base;
    __device__ __forceinline__ int operator()(int e) const { return base + P_(e); }
};
struct MapCol {
    int tx;
    __device__ __forceinline__ int operator()(int e) const { int b = (e << 2) + tx; return P_(b); }
};

// Stage 1: caller loaded v[r] (r = 0..7, element jj + 96r), no twiddle; write 8jj+s.
template<bool INV, class M>
static __device__ __forceinline__ void stage1_store(float2 v[8], float2* buf, int jj, M map) {
    dft8<INV>(v);
#pragma unroll
    for (int s = 0; s < 8; s++) buf[map(8*jj + s)] = v[s];
}

// Stage 2: read jj+96r, twiddle E[12*m*r] (m=jj%8, chained), dft8, write base+8s.
// Contains an internal __syncthreads between read and write (single buffer).
template<bool INV, class M>
static __device__ __forceinline__ void stage2(float2* buf, const float2* E, int jj, M map) {
    float2 v[8];
#pragma unroll
    for (int r = 0; r < 8; r++) v[r] = buf[map(jj + 96*r)];
    int m = jj & 7;
    float2 w1 = E[P_(12*m)];
    if (INV) w1.y = -w1.y;
    float2 w = w1;
#pragma unroll
    for (int r = 1; r < 8; r++) { v[r] = cmul(v[r], w); w = cmul(w, w1); }
    dft8<INV>(v);
    __syncthreads();
    int base = 8*jj - 7*m;
#pragma unroll
    for (int s = 0; s < 8; s++) buf[map(base + 8*s)] = v[s];
}

// Stage 3 (jj < 64 only): read jj+64r, twiddle E[jj*r] (chained), dft12 -> v natural order.
template<bool INV, class M>
static __device__ __forceinline__ void stage3(const float2* buf, const float2* E, int jj, M map, float2 v[12]) {
#pragma unroll
    for (int r = 0; r < 12; r++) v[r] = buf[map(jj + 64*r)];
    float2 w1 = E[P_(jj)];
    if (INV) w1.y = -w1.y;
    float2 w = w1;
#pragma unroll
    for (int r = 1; r < 12; r++) { v[r] = cmul(v[r], w); w = cmul(w, w1); }
    dft12<INV>(v);
}

// ---------------- Pass 1: pad + pack pairs + forward row FFT (512 rows/image) ----------------
__global__ __launch_bounds__(384) void k_row_fwd(const float* __restrict__ x)
{
    __shared__ float2 SB[BUF];
    __shared__ float2 SE[EBUF];
    int t = threadIdx.x;
    for (int i = t; i < NP; i += 384) SE[P_(i)] = g_E[i];
    int sub = t / 96, jj = t - sub * 96;
    int p = blockIdx.x >> 7;                    // /128
    int r = ((blockIdx.x & 127) << 2) + sub;    // row in [0,512)
    int y = PAD + r;
    const float* r1 = x + ((size_t)(2*p)     * HIN + r) * WIN;
    const float* r2 = x + ((size_t)(2*p + 1) * HIN + r) * WIN;
    float2 v[8];
#pragma unroll
    for (int rr = 0; rr < 8; rr++) {
        int xi = jj + 96*rr;
        float2 val = make_float2(0.f, 0.f);
        if (xi >= PAD && xi < PAD + WIN) {
            val.x = r1[xi - PAD];
            val.y = r2[xi - PAD];
        }
        v[rr] = val;
    }
    MapRow map; map.base = sub * LLEN;
    stage1_store<false>(v, SB, jj, map);
    __syncthreads();                            // SE + stage1 visible
    stage2<false>(SB, SE, jj, map);
    __syncthreads();
    if (jj < 64) {
        float2 u[12];
        stage3<false>(SB, SE, jj, map, u);
        float2* o = g_buf + ((size_t)p * NP + y) * NP;
#pragma unroll
        for (int s = 0; s < 12; s++) o[jj + 64*s] = u[s];
    }
}

// ---------------- Pass 2: column FFT * G * column IFFT (in place) ----------------
__global__ __launch_bounds__(384) void k_col(const float* __restrict__ w)
{
    __shared__ float2 SB[BUF];
    __shared__ float2 SE[EBUF];
    int t = threadIdx.x;
    for (int i = t; i < NP; i += 384) SE[P_(i)] = g_E[i];
    int tx = t & 3;
    int jj = t >> 2;                            // [0,96)
    int p = blockIdx.x / 192;
    int g = blockIdx.x - p * 192;
    int kx = (g << 2) + tx;
    float2* base = g_buf + (size_t)p * NP * NP;
    MapCol map; map.tx = tx;

    float2 v[8];
#pragma unroll
    for (int rr = 0; rr < 8; rr++) {
        int y = jj + 96*rr;
        float2 val = make_float2(0.f, 0.f);
        if (y >= PAD && y < PAD + NZROWS)
            val = base[(size_t)y * NP + kx];
        v[rr] = val;
    }
    stage1_store<false>(v, SB, jj, map);
    __syncthreads();
    stage2<false>(SB, SE, jj, map);
    __syncthreads();

    // filter coefficients for this kx (replicates reference exactly)
    int jp = (kx <= 384) ? kx : (NP - kx);
    int j2 = (jp == 0) ? 0 : ((jp == 384) ? 1 : (385 - jp));
    float2 D1[3], D2[3];
#pragma unroll
    for (int a = 0; a < 3; a++) {
        float2 s1 = make_float2(0.f, 0.f), s2 = make_float2(0.f, 0.f);
#pragma unroll
        for (int b = 0; b < 3; b++) {
            float wv = w[a * 3 + b];
            int i1 = (jp * b) % NP;
            int i2 = (j2 * b) % NP;
            float2 e1 = SE[P_(i1)], e2 = SE[P_(i2)];
            s1.x += wv * e1.x; s1.y += wv * e1.y;
            s2.x += wv * e2.x; s2.y += wv * e2.y;
        }
        D1[a] = s1; D2[a] = s2;
    }
    const float scale = 1.0f / ((float)NP * (float)NP);

    if (jj < 64) {
        float2 u[12];
        stage3<false>(SB, SE, jj, map, u);
#pragma unroll
        for (int s = 0; s < 12; s++) {
            int ky = jj + 64*s;
            float2 e1 = SE[P_(ky)];
            int k2i = 2 * ky; if (k2i >= NP) k2i -= NP;
            float2 e2 = SE[P_(k2i)];
            float2 c1 = cconj(e1), c2 = cconj(e2);
            float2 hp1 = cadd(D1[0], cadd(cmul(e1, D1[1]), cmul(e2, D1[2])));
            float2 hm1 = cadd(D1[0], cadd(cmul(c1, D1[1]), cmul(c2, D1[2])));
            float2 hp2 = cadd(D2[0], cadd(cmul(e1, D2[1]), cmul(e2, D2[2])));
            float2 hm2 = cadd(D2[0], cadd(cmul(c1, D2[1]), cmul(c2, D2[2])));
            float2 P = cmul(cmul(hp1, hm1), cmul(hp2, hm2));
            float inv = 1.0f / (P.x * P.x + P.y * P.y);
            float2 G = make_float2(P.x * inv, -P.y * inv);
            if (kx == 384)      G.y = 0.0f;    // irfft drops imag at Nyquist column
            else if (kx > 384)  G.y = -G.y;    // Hermitian mirror half
            G.x *= scale; G.y *= scale;
            u[s] = cmul(u[s], G);
        }
        // write filtered spectrum back (thread's read/write index sets identical -> no hazard)
#pragma unroll
        for (int s = 0; s < 12; s++) SB[map(jj + 64*s)] = u[s];
    }
    __syncthreads();

    // inverse FFT: stage1 must read-all before writing (single buffer)
    {
        float2 vi[8];
#pragma unroll
        for (int rr = 0; rr < 8; rr++) vi[rr] = SB[map(jj + 96*rr)];
        dft8<true>(vi);
        __syncthreads();
#pragma unroll
        for (int s = 0; s < 8; s++) SB[map(8*jj + s)] = vi[s];
    }
    __syncthreads();
    stage2<true>(SB, SE, jj, map);
    __syncthreads();
    if (jj < 64) {
        float2 u[12];
        stage3<true>(SB, SE, jj, map, u);
#pragma unroll
        for (int s = 0; s < 12; s++) {
            int y = jj + 64*s;
            base[(size_t)y * NP + kx] = u[s];
        }
    }
}

// ---------------- Pass 3: inverse row FFT + unpack pairs ----------------
__global__ __launch_bounds__(384) void k_row_inv(float* __restrict__ out)
{
    __shared__ float2 SB[BUF];
    __shared__ float2 SE[EBUF];
    int t = threadIdx.x;
    for (int i = t; i < NP; i += 384) SE[P_(i)] = g_E[i];
    int sub = t / 96, jj = t - sub * 96;
    int p = blockIdx.x / 192;
    int y = ((blockIdx.x - p * 192) << 2) + sub;
    const float2* in = g_buf + ((size_t)p * NP + y) * NP;
    float2 v[8];
#pragma unroll
    for (int rr = 0; rr < 8; rr++) v[rr] = in[jj + 96*rr];
    MapRow map; map.base = sub * LLEN;
    stage1_store<true>(v, SB, jj, map);
    __syncthreads();
    stage2<true>(SB, SE, jj, map);
    __syncthreads();
    if (jj < 64) {
        float2 u[12];
        stage3<true>(SB, SE, jj, map, u);
        float* o1 = out + ((size_t)(2*p)     * NP + y) * NP;
        float* o2 = out + ((size_t)(2*p + 1) * NP + y) * NP;
#pragma unroll
        for (int s = 0; s < 12; s++) {
            int xi = jj + 64*s;
            o1[xi] = u[s].x;
            o2[xi] = u[s].y;
        }
    }
}

extern "C" void kernel_launch(void* const* d_in, const int* in_sizes, int n_in,
                              void* d_out, int out_size)
{
    const float* x = (const float*)d_in[0];
    const float* w = (const float*)d_in[1];
    if (n_in >= 2 && in_sizes[0] == 9) {  // safety: metadata order w,x
        const float* tmp = x; x = w; w = tmp;
    }
    float* out = (float*)d_out;

    k_init_E<<<1, NP>>>();
    k_row_fwd<<<NPAIR * NZROWS / 4, 384>>>(x);
    k_col    <<<NPAIR * 192, 384>>>(w);
    k_row_inv<<<NPAIR * NP / 4, 384>>>(out);
}

// round 7
// speedup vs baseline: 1.8504x; 1.0879x over previous
#include <cuda_runtime.h>
#include <cuda_fp16.h>
#include <math.h>

#define NPAIR 32      // 64 real batches packed as 32 complex images
#define HIN   512
#define WIN   512
#define NP    768     // padded size (both dims)
#define PAD   128
#define NZROWS 512    // nonzero padded rows: y in [PAD, PAD+512)

// padded smem element index: +1 float2 per 16 to break power-of-2 stride conflicts
#define P_(i) ((i) + ((i) >> 4))

#define BUF   3264    // block-wide float2 data buffer: >= P_(3071)+1
#define LLEN  816     // per-line stride in row kernels: >= P_(767)+1
#define EBUF  816

__device__ __half2 g_buf[NPAIR * NP * NP];  // 75 MB fp16 complex scratch
__device__ float2  g_E[NP];                 // e^{-2*pi*i*m/768}

static __device__ __forceinline__ float2 cmul(float2 a, float2 b) {
    return make_float2(a.x*b.x - a.y*b.y, a.x*b.y + a.y*b.x);
}
static __device__ __forceinline__ float2 cadd(float2 a, float2 b) { return make_float2(a.x+b.x, a.y+b.y); }
static __device__ __forceinline__ float2 csub(float2 a, float2 b) { return make_float2(a.x-b.x, a.y-b.y); }
static __device__ __forceinline__ float2 cconj(float2 a) { return make_float2(a.x, -a.y); }
static __device__ __forceinline__ float2 mul_mi(float2 a) { return make_float2(a.y, -a.x); }  // *(-i)
static __device__ __forceinline__ float2 mul_pi(float2 a) { return make_float2(-a.y, a.x); }  // *(+i)

static __device__ __forceinline__ float2 ldh(const __half2* p) { return __half22float2(*p); }
static __device__ __forceinline__ void sth(__half2* p, float2 v) { *p = __floats2half2_rn(v.x, v.y); }

__global__ void k_init_E() {
    int t = threadIdx.x;
    if (t < NP) {
        double a = -2.0 * 3.14159265358979323846 * (double)t / (double)NP;
        g_E[t] = make_float2((float)cos(a), (float)sin(a));
    }
}

// ---------------- register DFT kernels ----------------
template<bool INV>
static __device__ __forceinline__ void dft4(float2 v[4]) {
    float2 t0 = cadd(v[0], v[2]), t1 = csub(v[0], v[2]);
    float2 t2 = cadd(v[1], v[3]), t3 = csub(v[1], v[3]);
    float2 jt3 = INV ? mul_pi(t3) : mul_mi(t3);
    v[0] = cadd(t0, t2); v[2] = csub(t0, t2);
    v[1] = cadd(t1, jt3); v[3] = csub(t1, jt3);
}

template<bool INV>
static __device__ __forceinline__ void dft8(float2 v[8]) {
    float2 e[4] = {v[0], v[2], v[4], v[6]};
    float2 o[4] = {v[1], v[3], v[5], v[7]};
    dft4<INV>(e); dft4<INV>(o);
    const float rh = 0.70710678118654752f;
    o[1] = cmul(o[1], make_float2(rh, INV ? rh : -rh));
    o[2] = INV ? mul_pi(o[2]) : mul_mi(o[2]);
    o[3] = cmul(o[3], make_float2(-rh, INV ? rh : -rh));
#pragma unroll
    for (int k = 0; k < 4; k++) { v[k] = cadd(e[k], o[k]); v[k+4] = csub(e[k], o[k]); }
}

// 12-point DFT, natural-order in and out.  12 = 4 x 3 Cooley-Tukey.
template<bool INV>
static __device__ __forceinline__ void dft12(float2 v[12]) {
    const float H = 0.5f, S = 0.8660254037844386f;
    float2 c0[4], c1[4], c2[4];
    {
        float2 b[4];
        b[0]=v[0]; b[1]=v[3]; b[2]=v[6]; b[3]=v[9];  dft4<INV>(b);
        c0[0]=b[0]; c0[1]=b[1]; c0[2]=b[2]; c0[3]=b[3];
        b[0]=v[1]; b[1]=v[4]; b[2]=v[7]; b[3]=v[10]; dft4<INV>(b);
        c1[0]=b[0]; c1[1]=b[1]; c1[2]=b[2]; c1[3]=b[3];
        b[0]=v[2]; b[1]=v[5]; b[2]=v[8]; b[3]=v[11]; dft4<INV>(b);
        c2[0]=b[0]; c2[1]=b[1]; c2[2]=b[2]; c2[3]=b[3];
    }
    const float sgn = INV ? 1.f : -1.f;
    c1[1] = cmul(c1[1], make_float2(S, sgn*H));
    c1[2] = cmul(c1[2], make_float2(H, sgn*S));
    c1[3] = INV ? mul_pi(c1[3]) : mul_mi(c1[3]);
    c2[1] = cmul(c2[1], make_float2(H,  sgn*S));
    c2[2] = cmul(c2[2], make_float2(-H, sgn*S));
    c2[3] = make_float2(-c2[3].x, -c2[3].y);
    const float d = INV ? S : -S;
#pragma unroll
    for (int k1 = 0; k1 < 4; k1++) {
        float2 t = cadd(c1[k1], c2[k1]);
        float2 u = csub(c1[k1], c2[k1]);
        float2 x0 = cadd(c0[k1], t);
        float2 m = make_float2(c0[k1].x - 0.5f*t.x, c0[k1].y - 0.5f*t.y);
        float2 idu = make_float2(-d*u.y, d*u.x);
        v[k1]     = x0;
        v[4 + k1] = cadd(m, idu);
        v[8 + k1] = csub(m, idu);
    }
}

// ---------------- Stockham stages: 768 = 8(NS=1) * 8(NS=8) * 12(NS=64) ----------------
struct MapRow {
    int base;
    __device__ __forceinline__ int operator()(int e) const { return base + P_(e); }
};
struct MapCol {
    int tx;
    __device__ __forceinline__ int operator()(int e) const { int b = (e << 2) + tx; return P_(b); }
};

// Stage 1: caller loaded v[r] (r = 0..7, element jj + 96r), no twiddle; write 8jj+s.
template<bool INV, class M>
static __device__ __forceinline__ void stage1_store(float2 v[8], float2* buf, int jj, M map) {
    dft8<INV>(v);
#pragma unroll
    for (int s = 0; s < 8; s++) buf[map(8*jj + s)] = v[s];
}

// Stage 2: read jj+96r, twiddle E[12*m*r] (m=jj%8, chained), dft8, write base+8s.
// Contains an internal __syncthreads between read and write (single buffer).
template<bool INV, class M>
static __device__ __forceinline__ void stage2(float2* buf, const float2* E, int jj, M map) {
    float2 v[8];
#pragma unroll
    for (int r = 0; r < 8; r++) v[r] = buf[map(jj + 96*r)];
    int m = jj & 7;
    float2 w1 = E[P_(12*m)];
    if (INV) w1.y = -w1.y;
    float2 w = w1;
#pragma unroll
    for (int r = 1; r < 8; r++) { v[r] = cmul(v[r], w); w = cmul(w, w1); }
    dft8<INV>(v);
    __syncthreads();
    int base = 8*jj - 7*m;
#pragma unroll
    for (int s = 0; s < 8; s++) buf[map(base + 8*s)] = v[s];
}

// Stage 3 (jj < 64 only): read jj+64r, twiddle E[jj*r] (chained), dft12 -> v natural order.
template<bool INV, class M>
static __device__ __forceinline__ void stage3(const float2* buf, const float2* E, int jj, M map, float2 v[12]) {
#pragma unroll
    for (int r = 0; r < 12; r++) v[r] = buf[map(jj + 64*r)];
    float2 w1 = E[P_(jj)];
    if (INV) w1.y = -w1.y;
    float2 w = w1;
#pragma unroll
    for (int r = 1; r < 12; r++) { v[r] = cmul(v[r], w); w = cmul(w, w1); }
    dft12<INV>(v);
}

// ---------------- Pass 1: pad + pack pairs + forward row FFT (512 rows/image) ----------------
__global__ __launch_bounds__(384) void k_row_fwd(const float* __restrict__ x)
{
    __shared__ float2 SB[BUF];
    __shared__ float2 SE[EBUF];
    int t = threadIdx.x;
    for (int i = t; i < NP; i += 384) SE[P_(i)] = g_E[i];
    int sub = t / 96, jj = t - sub * 96;
    int p = blockIdx.x >> 7;                    // /128
    int r = ((blockIdx.x & 127) << 2) + sub;    // row in [0,512)
    int y = PAD + r;
    const float* r1 = x + ((size_t)(2*p)     * HIN + r) * WIN;
    const float* r2 = x + ((size_t)(2*p + 1) * HIN + r) * WIN;
    float2 v[8];
#pragma unroll
    for (int rr = 0; rr < 8; rr++) {
        int xi = jj + 96*rr;
        float2 val = make_float2(0.f, 0.f);
        if (xi >= PAD && xi < PAD + WIN) {
            val.x = r1[xi - PAD];
            val.y = r2[xi - PAD];
        }
        v[rr] = val;
    }
    MapRow map; map.base = sub * LLEN;
    stage1_store<false>(v, SB, jj, map);
    __syncthreads();                            // SE + stage1 visible
    stage2<false>(SB, SE, jj, map);
    __syncthreads();
    if (jj < 64) {
        float2 u[12];
        stage3<false>(SB, SE, jj, map, u);
        __half2* o = g_buf + ((size_t)p * NP + y) * NP;
#pragma unroll
        for (int s = 0; s < 12; s++) sth(o + jj + 64*s, u[s]);
    }
}

// ---------------- Pass 2: column FFT * G * column IFFT (in place) ----------------
__global__ __launch_bounds__(384) void k_col(const float* __restrict__ w)
{
    __shared__ float2 SB[BUF];
    __shared__ float2 SE[EBUF];
    int t = threadIdx.x;
    for (int i = t; i < NP; i += 384) SE[P_(i)] = g_E[i];
    int tx = t & 3;
    int jj = t >> 2;                            // [0,96)
    int p = blockIdx.x / 192;
    int g = blockIdx.x - p * 192;
    int kx = (g << 2) + tx;
    __half2* base = g_buf + (size_t)p * NP * NP;
    MapCol map; map.tx = tx;

    float2 v[8];
#pragma unroll
    for (int rr = 0; rr < 8; rr++) {
        int y = jj + 96*rr;
        float2 val = make_float2(0.f, 0.f);
        if (y >= PAD && y < PAD + NZROWS)
            val = ldh(base + (size_t)y * NP + kx);
        v[rr] = val;
    }
    stage1_store<false>(v, SB, jj, map);
    __syncthreads();
    stage2<false>(SB, SE, jj, map);
    __syncthreads();

    // filter coefficients for this kx (replicates reference exactly)
    int jp = (kx <= 384) ? kx : (NP - kx);
    int j2 = (jp == 0) ? 0 : ((jp == 384) ? 1 : (385 - jp));
    float2 D1[3], D2[3];
#pragma unroll
    for (int a = 0; a < 3; a++) {
        float2 s1 = make_float2(0.f, 0.f), s2 = make_float2(0.f, 0.f);
#pragma unroll
        for (int b = 0; b < 3; b++) {
            float wv = w[a * 3 + b];
            int i1 = (jp * b) % NP;
            int i2 = (j2 * b) % NP;
            float2 e1 = SE[P_(i1)], e2 = SE[P_(i2)];
            s1.x += wv * e1.x; s1.y += wv * e1.y;
            s2.x += wv * e2.x; s2.y += wv * e2.y;
        }
        D1[a] = s1; D2[a] = s2;
    }
    const float scale = 1.0f / ((float)NP * (float)NP);

    if (jj < 64) {
        float2 u[12];
        stage3<false>(SB, SE, jj, map, u);
#pragma unroll
        for (int s = 0; s < 12; s++) {
            int ky = jj + 64*s;
            float2 e1 = SE[P_(ky)];
            int k2i = 2 * ky; if (k2i >= NP) k2i -= NP;
            float2 e2 = SE[P_(k2i)];
            float2 c1 = cconj(e1), c2 = cconj(e2);
            float2 hp1 = cadd(D1[0], cadd(cmul(e1, D1[1]), cmul(e2, D1[2])));
            float2 hm1 = cadd(D1[0], cadd(cmul(c1, D1[1]), cmul(c2, D1[2])));
            float2 hp2 = cadd(D2[0], cadd(cmul(e1, D2[1]), cmul(e2, D2[2])));
            float2 hm2 = cadd(D2[0], cadd(cmul(c1, D2[1]), cmul(c2, D2[2])));
            float2 P = cmul(cmul(hp1, hm1), cmul(hp2, hm2));
            float inv = 1.0f / (P.x * P.x + P.y * P.y);
            float2 G = make_float2(P.x * inv, -P.y * inv);
            if (kx == 384)      G.y = 0.0f;    // irfft drops imag at Nyquist column
            else if (kx > 384)  G.y = -G.y;    // Hermitian mirror half
            G.x *= scale; G.y *= scale;
            u[s] = cmul(u[s], G);
        }
        // write filtered spectrum back (thread's read/write index sets identical -> no hazard)
#pragma unroll
        for (int s = 0; s < 12; s++) SB[map(jj + 64*s)] = u[s];
    }
    __syncthreads();

    // inverse FFT: stage1 must read-all before writing (single buffer)
    {
        float2 vi[8];
#pragma unroll
        for (int rr = 0; rr < 8; rr++) vi[rr] = SB[map(jj + 96*rr)];
        dft8<true>(vi);
        __syncthreads();
#pragma unroll
        for (int s = 0; s < 8; s++) SB[map(8*jj + s)] = vi[s];
    }
    __syncthreads();
    stage2<true>(SB, SE, jj, map);
    __syncthreads();
    if (jj < 64) {
        float2 u[12];
        stage3<true>(SB, SE, jj, map, u);
#pragma unroll
        for (int s = 0; s < 12; s++) {
            int y = jj + 64*s;
            sth(base + (size_t)y * NP + kx, u[s]);
        }
    }
}

// ---------------- Pass 3: inverse row FFT + unpack pairs ----------------
__global__ __launch_bounds__(384) void k_row_inv(float* __restrict__ out)
{
    __shared__ float2 SB[BUF];
    __shared__ float2 SE[EBUF];
    int t = threadIdx.x;
    for (int i = t; i < NP; i += 384) SE[P_(i)] = g_E[i];
    int sub = t / 96, jj = t - sub * 96;
    int p = blockIdx.x / 192;
    int y = ((blockIdx.x - p * 192) << 2) + sub;
    const __half2* in = g_buf + ((size_t)p * NP + y) * NP;
    float2 v[8];
#pragma unroll
    for (int rr = 0; rr < 8; rr++) v[rr] = ldh(in + jj + 96*rr);
    MapRow map; map.base = sub * LLEN;
    stage1_store<true>(v, SB, jj, map);
    __syncthreads();
    stage2<true>(SB, SE, jj, map);
    __syncthreads();
    if (jj < 64) {
        float2 u[12];
        stage3<true>(SB, SE, jj, map, u);
        float* o1 = out + ((size_t)(2*p)     * NP + y) * NP;
        float* o2 = out + ((size_t)(2*p + 1) * NP + y) * NP;
#pragma unroll
        for (int s = 0; s < 12; s++) {
            int xi = jj + 64*s;
            o1[xi] = u[s].x;
            o2[xi] = u[s].y;
        }
    }
}

extern "C" void kernel_launch(void* const* d_in, const int* in_sizes, int n_in,
                              void* d_out, int out_size)
{
    const float* x = (const float*)d_in[0];
    const float* w = (const float*)d_in[1];
    if (n_in >= 2 && in_sizes[0] == 9) {  // safety: metadata order w,x
        const float* tmp = x; x = w; w = tmp;
    }
    float* out = (float*)d_out;

    k_init_E<<<1, NP>>>();
    k_row_fwd<<<NPAIR * NZROWS / 4, 384>>>(x);
    k_col    <<<NPAIR * 192, 384>>>(w);
    k_row_inv<<<NPAIR * NP / 4, 384>>>(out);
}

// round 8
// speedup vs baseline: 1.8809x; 1.0165x over previous
#include <cuda_runtime.h>
#include <cuda_fp16.h>
#include <math.h>

#define NPAIR 32      // 64 real batches packed as 32 complex images
#define HIN   512
#define WIN   512
#define NP    768     // padded size (both dims)
#define PAD   128
#define NZROWS 512    // nonzero padded rows: y in [PAD, PAD+512)

// padded smem element index: +1 float2 per 16 to break power-of-2 stride conflicts
#define P_(i) ((i) + ((i) >> 4))

#define BUF   3264    // block-wide float2 data buffer: >= P_(3071)+1
#define LLEN  816     // per-line stride in row kernels: >= P_(767)+1
#define EBUF  816

__device__ __half2 g_buf[NPAIR * NP * NP];  // 75 MB fp16 complex scratch
__device__ float2  g_E[NP];                 // e^{-2*pi*i*m/768}

static __device__ __forceinline__ float2 cmul(float2 a, float2 b) {
    return make_float2(a.x*b.x - a.y*b.y, a.x*b.y + a.y*b.x);
}
static __device__ __forceinline__ float2 cadd(float2 a, float2 b) { return make_float2(a.x+b.x, a.y+b.y); }
static __device__ __forceinline__ float2 csub(float2 a, float2 b) { return make_float2(a.x-b.x, a.y-b.y); }
static __device__ __forceinline__ float2 cconj(float2 a) { return make_float2(a.x, -a.y); }
static __device__ __forceinline__ float2 mul_mi(float2 a) { return make_float2(a.y, -a.x); }  // *(-i)
static __device__ __forceinline__ float2 mul_pi(float2 a) { return make_float2(-a.y, a.x); }  // *(+i)

static __device__ __forceinline__ float2 ldh(const __half2* p) { return __half22float2(*p); }
static __device__ __forceinline__ void sth(__half2* p, float2 v) { *p = __floats2half2_rn(v.x, v.y); }

__global__ void k_init_E() {
    int t = threadIdx.x;
    if (t < NP) {
        double a = -2.0 * 3.14159265358979323846 * (double)t / (double)NP;
        g_E[t] = make_float2((float)cos(a), (float)sin(a));
    }
}

// ---------------- register DFT kernels ----------------
template<bool INV>
static __device__ __forceinline__ void dft4(float2 v[4]) {
    float2 t0 = cadd(v[0], v[2]), t1 = csub(v[0], v[2]);
    float2 t2 = cadd(v[1], v[3]), t3 = csub(v[1], v[3]);
    float2 jt3 = INV ? mul_pi(t3) : mul_mi(t3);
    v[0] = cadd(t0, t2); v[2] = csub(t0, t2);
    v[1] = cadd(t1, jt3); v[3] = csub(t1, jt3);
}

template<bool INV>
static __device__ __forceinline__ void dft8(float2 v[8]) {
    float2 e[4] = {v[0], v[2], v[4], v[6]};
    float2 o[4] = {v[1], v[3], v[5], v[7]};
    dft4<INV>(e); dft4<INV>(o);
    const float rh = 0.70710678118654752f;
    o[1] = cmul(o[1], make_float2(rh, INV ? rh : -rh));
    o[2] = INV ? mul_pi(o[2]) : mul_mi(o[2]);
    o[3] = cmul(o[3], make_float2(-rh, INV ? rh : -rh));
#pragma unroll
    for (int k = 0; k < 4; k++) { v[k] = cadd(e[k], o[k]); v[k+4] = csub(e[k], o[k]); }
}

// 12-point DFT, natural-order in and out.  12 = 4 x 3 Cooley-Tukey.
template<bool INV>
static __device__ __forceinline__ void dft12(float2 v[12]) {
    const float H = 0.5f, S = 0.8660254037844386f;
    float2 c0[4], c1[4], c2[4];
    {
        float2 b[4];
        b[0]=v[0]; b[1]=v[3]; b[2]=v[6]; b[3]=v[9];  dft4<INV>(b);
        c0[0]=b[0]; c0[1]=b[1]; c0[2]=b[2]; c0[3]=b[3];
        b[0]=v[1]; b[1]=v[4]; b[2]=v[7]; b[3]=v[10]; dft4<INV>(b);
        c1[0]=b[0]; c1[1]=b[1]; c1[2]=b[2]; c1[3]=b[3];
        b[0]=v[2]; b[1]=v[5]; b[2]=v[8]; b[3]=v[11]; dft4<INV>(b);
        c2[0]=b[0]; c2[1]=b[1]; c2[2]=b[2]; c2[3]=b[3];
    }
    const float sgn = INV ? 1.f : -1.f;
    c1[1] = cmul(c1[1], make_float2(S, sgn*H));
    c1[2] = cmul(c1[2], make_float2(H, sgn*S));
    c1[3] = INV ? mul_pi(c1[3]) : mul_mi(c1[3]);
    c2[1] = cmul(c2[1], make_float2(H,  sgn*S));
    c2[2] = cmul(c2[2], make_float2(-H, sgn*S));
    c2[3] = make_float2(-c2[3].x, -c2[3].y);
    const float d = INV ? S : -S;
#pragma unroll
    for (int k1 = 0; k1 < 4; k1++) {
        float2 t = cadd(c1[k1], c2[k1]);
        float2 u = csub(c1[k1], c2[k1]);
        float2 x0 = cadd(c0[k1], t);
        float2 m = make_float2(c0[k1].x - 0.5f*t.x, c0[k1].y - 0.5f*t.y);
        float2 idu = make_float2(-d*u.y, d*u.x);
        v[k1]     = x0;
        v[4 + k1] = cadd(m, idu);
        v[8 + k1] = csub(m, idu);
    }
}

// ---------------- Stockham stages: 768 = 8(NS=1) * 12(NS=8) * 8(NS=96) ----------------
// Stage 1 (96 thr/line): in regs v[r] = x[j+96r]; dft8; write 8j+s.
// Stage 2 (64 thr/line): read j+64r (r<12); twiddle E[8m]^r (m=j&7); dft12; write 12j-11m+8s.
// Stage 3 (96 thr/line): read j+96r (r<8); twiddle E[j]^r; dft8 -> X[j+96s] in regs.
struct MapRow {
    int base;
    __device__ __forceinline__ int operator()(int e) const { return base + P_(e); }
};
struct MapCol {
    int tx;
    __device__ __forceinline__ int operator()(int e) const { int b = (e << 2) + tx; return P_(b); }
};

template<bool INV, class M>
static __device__ __forceinline__ void stage1_store(float2 v[8], float2* buf, int j, M map) {
    dft8<INV>(v);
#pragma unroll
    for (int s = 0; s < 8; s++) buf[map(8*j + s)] = v[s];
}

// active = (j < 64). ALL threads must call (contains block barrier).
template<bool INV, class M>
static __device__ __forceinline__ void stage2_r12(float2* buf, const float2* E, int j, bool active, M map) {
    float2 v[12];
    int m = j & 7;
    if (active) {
#pragma unroll
        for (int r = 0; r < 12; r++) v[r] = buf[map(j + 64*r)];
        float2 w1 = E[P_(8*m)];
        if (INV) w1.y = -w1.y;
        float2 w = w1;
#pragma unroll
        for (int r = 1; r < 12; r++) { v[r] = cmul(v[r], w); w = cmul(w, w1); }
        dft12<INV>(v);
    }
    __syncthreads();
    if (active) {
        int base = 12*j - 11*m;
#pragma unroll
        for (int s = 0; s < 12; s++) buf[map(base + 8*s)] = v[s];
    }
    __syncthreads();
}

// output in v: v[s] = X[j + 96 s]
template<bool INV, class M>
static __device__ __forceinline__ void stage3_r8(const float2* buf, const float2* E, int j, M map, float2 v[8]) {
#pragma unroll
    for (int r = 0; r < 8; r++) v[r] = buf[map(j + 96*r)];
    float2 w1 = E[P_(j)];
    if (INV) w1.y = -w1.y;
    float2 w = w1;
#pragma unroll
    for (int r = 1; r < 8; r++) { v[r] = cmul(v[r], w); w = cmul(w, w1); }
    dft8<INV>(v);
}

// ---------------- Pass 1: pad + pack pairs + forward row FFT (512 rows/image) ----------------
__global__ __launch_bounds__(384) void k_row_fwd(const float* __restrict__ x)
{
    __shared__ float2 SB[BUF];
    __shared__ float2 SE[EBUF];
    int t = threadIdx.x;
    for (int i = t; i < NP; i += 384) SE[P_(i)] = g_E[i];
    int sub = t / 96, jj = t - sub * 96;
    int p = blockIdx.x >> 7;                    // /128
    int r = ((blockIdx.x & 127) << 2) + sub;    // row in [0,512)
    int y = PAD + r;
    const float* r1 = x + ((size_t)(2*p)     * HIN + r) * WIN;
    const float* r2 = x + ((size_t)(2*p + 1) * HIN + r) * WIN;
    float2 v[8];
#pragma unroll
    for (int rr = 0; rr < 8; rr++) {
        int xi = jj + 96*rr;
        float2 val = make_float2(0.f, 0.f);
        if (xi >= PAD && xi < PAD + WIN) {
            val.x = r1[xi - PAD];
            val.y = r2[xi - PAD];
        }
        v[rr] = val;
    }
    MapRow map; map.base = sub * LLEN;
    stage1_store<false>(v, SB, jj, map);
    __syncthreads();                            // SE + stage1 visible
    stage2_r12<false>(SB, SE, jj, jj < 64, map);
    float2 u[8];
    stage3_r8<false>(SB, SE, jj, map, u);
    __half2* o = g_buf + ((size_t)p * NP + y) * NP;
#pragma unroll
    for (int s = 0; s < 8; s++) sth(o + jj + 96*s, u[s]);
}

// ---------------- Pass 2: column FFT * G * column IFFT (in place) ----------------
__global__ __launch_bounds__(384) void k_col(const float* __restrict__ w)
{
    __shared__ float2 SB[BUF];
    __shared__ float2 SE[EBUF];
    int t = threadIdx.x;
    for (int i = t; i < NP; i += 384) SE[P_(i)] = g_E[i];
    int tx = t & 3;
    int jj = t >> 2;                            // [0,96)
    int p = blockIdx.x / 192;
    int g = blockIdx.x - p * 192;
    int kx = (g << 2) + tx;
    __half2* base = g_buf + (size_t)p * NP * NP;
    MapCol map; map.tx = tx;

    float2 v[8];
#pragma unroll
    for (int rr = 0; rr < 8; rr++) {
        int y = jj + 96*rr;
        float2 val = make_float2(0.f, 0.f);
        if (y >= PAD && y < PAD + NZROWS)
            val = ldh(base + (size_t)y * NP + kx);
        v[rr] = val;
    }
    stage1_store<false>(v, SB, jj, map);
    __syncthreads();
    stage2_r12<false>(SB, SE, jj, jj < 64, map);
    float2 u[8];
    stage3_r8<false>(SB, SE, jj, map, u);       // u[s] = spectrum at ky = jj+96s

    // filter coefficients for this kx (replicates reference exactly)
    int jp = (kx <= 384) ? kx : (NP - kx);
    int j2 = (jp == 0) ? 0 : ((jp == 384) ? 1 : (385 - jp));
    float2 D1[3], D2[3];
#pragma unroll
    for (int a = 0; a < 3; a++) {
        float2 s1 = make_float2(0.f, 0.f), s2 = make_float2(0.f, 0.f);
#pragma unroll
        for (int b = 0; b < 3; b++) {
            float wv = w[a * 3 + b];
            int i1 = (jp * b) % NP;
            int i2 = (j2 * b) % NP;
            float2 e1 = SE[P_(i1)], e2 = SE[P_(i2)];
            s1.x += wv * e1.x; s1.y += wv * e1.y;
            s2.x += wv * e2.x; s2.y += wv * e2.y;
        }
        D1[a] = s1; D2[a] = s2;
    }
    const float scale = 1.0f / ((float)NP * (float)NP);
#pragma unroll
    for (int s = 0; s < 8; s++) {
        int ky = jj + 96*s;
        float2 e1 = SE[P_(ky)];
        int k2i = 2 * ky; if (k2i >= NP) k2i -= NP;
        float2 e2 = SE[P_(k2i)];
        float2 c1 = cconj(e1), c2 = cconj(e2);
        float2 hp1 = cadd(D1[0], cadd(cmul(e1, D1[1]), cmul(e2, D1[2])));
        float2 hm1 = cadd(D1[0], cadd(cmul(c1, D1[1]), cmul(c2, D1[2])));
        float2 hp2 = cadd(D2[0], cadd(cmul(e1, D2[1]), cmul(e2, D2[2])));
        float2 hm2 = cadd(D2[0], cadd(cmul(c1, D2[1]), cmul(c2, D2[2])));
        float2 P = cmul(cmul(hp1, hm1), cmul(hp2, hm2));
        float inv = 1.0f / (P.x * P.x + P.y * P.y);
        float2 G = make_float2(P.x * inv, -P.y * inv);
        if (kx == 384)      G.y = 0.0f;    // irfft drops imag at Nyquist column
        else if (kx > 384)  G.y = -G.y;    // Hermitian mirror half
        G.x *= scale; G.y *= scale;
        u[s] = cmul(u[s], G);
    }

    // inverse FFT: u[r] is exactly X[jj + 96r] = stage-1 input -> fuse in registers
    dft8<true>(u);
    __syncthreads();                            // all forward stage-3 reads of SB done
#pragma unroll
    for (int s = 0; s < 8; s++) SB[map(8*jj + s)] = u[s];
    __syncthreads();
    stage2_r12<true>(SB, SE, jj, jj < 64, map);
    float2 z[8];
    stage3_r8<true>(SB, SE, jj, map, z);
#pragma unroll
    for (int s = 0; s < 8; s++) {
        int y = jj + 96*s;
        sth(base + (size_t)y * NP + kx, z[s]);
    }
}

// ---------------- Pass 3: inverse row FFT + unpack pairs ----------------
__global__ __launch_bounds__(384) void k_row_inv(float* __restrict__ out)
{
    __shared__ float2 SB[BUF];
    __shared__ float2 SE[EBUF];
    int t = threadIdx.x;
    for (int i = t; i < NP; i += 384) SE[P_(i)] = g_E[i];
    int sub = t / 96, jj = t - sub * 96;
    int p = blockIdx.x / 192;
    int y = ((blockIdx.x - p * 192) << 2) + sub;
    const __half2* in = g_buf + ((size_t)p * NP + y) * NP;
    float2 v[8];
#pragma unroll
    for (int rr = 0; rr < 8; rr++) v[rr] = ldh(in + jj + 96*rr);
    MapRow map; map.base = sub * LLEN;
    stage1_store<true>(v, SB, jj, map);
    __syncthreads();
    stage2_r12<true>(SB, SE, jj, jj < 64, map);
    float2 u[8];
    stage3_r8<true>(SB, SE, jj, map, u);
    float* o1 = out + ((size_t)(2*p)     * NP + y) * NP;
    float* o2 = out + ((size_t)(2*p + 1) * NP + y) * NP;
#pragma unroll
    for (int s = 0; s < 8; s++) {
        int xi = jj + 96*s;
        o1[xi] = u[s].x;
        o2[xi] = u[s].y;
    }
}

extern "C" void kernel_launch(void* const* d_in, const int* in_sizes, int n_in,
                              void* d_out, int out_size)
{
    const float* x = (const float*)d_in[0];
    const float* w = (const float*)d_in[1];
    if (n_in >= 2 && in_sizes[0] == 9) {  // safety: metadata order w,x
        const float* tmp = x; x = w; w = tmp;
    }
    float* out = (float*)d_out;

    k_init_E<<<1, NP>>>();
    k_row_fwd<<<NPAIR * NZROWS / 4, 384>>>(x);
    k_col    <<<NPAIR * 192, 384>>>(w);
    k_row_inv<<<NPAIR * NP / 4, 384>>>(out);
}